// round 16
// baseline (speedup 1.0000x reference)
#include <cuda_runtime.h>
#include <cuda_fp16.h>
#include <math.h>
#include <stdint.h>

// Problem shape
#define BB 8
#define TT 2048
#define CC 1024
#define HH 16
#define DD 64
#define MTOT (BB*TT)      // 16384
#define KDIM 1024
#define N_QKV 3072
#define N_PROJ 1024

// ---------------- scratch (__device__ globals; no allocation allowed) -------
__device__ __half g_qkv [(size_t)MTOT * N_QKV];   // fp16: phi_q | phi_k*m | v*m
__device__ __half g_xh  [(size_t)MTOT * KDIM];
__device__ __half g_wah [(size_t)N_QKV * KDIM];   // transposed [N,K], fp16
__device__ __half g_wph [(size_t)N_PROJ * KDIM];
__device__ __half g_yh  [(size_t)MTOT * CC];
__device__ float  g_kvp[8 * BB*HH * DD*DD];
__device__ float  g_ksp[8 * BB*HH * DD];
__device__ __half g_kvh[BB*HH * DD*DD];           // kv state fp16 hi
__device__ __half g_kvl[BB*HH * DD*DD];           // kv state fp16 lo
__device__ float  g_ks [BB*HH * DD];

// ---------------- helpers ----------------------------------------------------
__device__ __forceinline__ uint32_t smem_u32(const void* p) {
    uint32_t a;
    asm("{ .reg .u64 t; cvta.to.shared.u64 t, %1; cvt.u32.u64 %0, t; }"
        : "=r"(a) : "l"(p));
    return a;
}
__device__ __forceinline__ void cpasync16(uint32_t dst, const void* src) {
    asm volatile("cp.async.cg.shared.global [%0], [%1], 16;" :: "r"(dst), "l"(src));
}
#define CP_COMMIT() asm volatile("cp.async.commit_group;" ::: "memory")
#define CP_WAIT1()  asm volatile("cp.async.wait_group 1;" ::: "memory")
#define CP_WAIT0()  asm volatile("cp.async.wait_group 0;" ::: "memory")

__device__ __forceinline__ void ldsm4(uint32_t (&r)[4], uint32_t addr) {
    asm volatile("ldmatrix.sync.aligned.m8n8.x4.shared.b16 {%0,%1,%2,%3}, [%4];"
                 : "=r"(r[0]), "=r"(r[1]), "=r"(r[2]), "=r"(r[3]) : "r"(addr));
}
__device__ __forceinline__ void ldsm4t(uint32_t (&r)[4], uint32_t addr) {
    asm volatile("ldmatrix.sync.aligned.m8n8.x4.trans.shared.b16 {%0,%1,%2,%3}, [%4];"
                 : "=r"(r[0]), "=r"(r[1]), "=r"(r[2]), "=r"(r[3]) : "r"(addr));
}
__device__ __forceinline__ void mma16816(float (&c)[4], const uint32_t (&a)[4],
                                         uint32_t b0, uint32_t b1) {
    asm volatile(
        "mma.sync.aligned.m16n8k16.row.col.f32.f16.f16.f32 "
        "{%0,%1,%2,%3}, {%4,%5,%6,%7}, {%8,%9}, {%0,%1,%2,%3};"
        : "+f"(c[0]), "+f"(c[1]), "+f"(c[2]), "+f"(c[3])
        : "r"(a[0]), "r"(a[1]), "r"(a[2]), "r"(a[3]), "r"(b0), "r"(b1));
}

// FFMA-only exp(x) (no MUFU), rel err ~2.4e-6.
__device__ __forceinline__ float fexp(float x) {
    x = fmaxf(x, -80.f);
    float t = x * 1.4426950408889634f;
    float r = t + 12582912.0f;
    int   n = __float_as_int(r) - 0x4B400000;
    float f = t - (r - 12582912.0f);
    float g = f * 0.6931471805599453f;
    float p = fmaf(g, 0.008333333f, 0.041666667f);
    p = fmaf(g, p, 0.166666667f);
    p = fmaf(g, p, 0.5f);
    p = fmaf(g, p, 1.0f);
    p = fmaf(g, p, 1.0f);
    return __int_as_float(__float_as_int(p) + (n << 23));
}

// SW128 swizzle for 128B rows (Swizzle<3,4,3>)
__device__ __forceinline__ uint32_t swz128(uint32_t o) {
    return o ^ ((o >> 3) & 0x70);
}

// ---------------- conversion kernels ----------------------------------------
__global__ __launch_bounds__(256)
void conv_x_kernel(const float4* __restrict__ in, uint2* __restrict__ hi) {
    size_t i = (size_t)blockIdx.x * blockDim.x + threadIdx.x;
    float4 v = in[i];
    __half h0 = __float2half(v.x), h1 = __float2half(v.y);
    __half h2 = __float2half(v.z), h3 = __float2half(v.w);
    uint32_t ha = (uint32_t)__half_as_ushort(h0) | ((uint32_t)__half_as_ushort(h1) << 16);
    uint32_t hb = (uint32_t)__half_as_ushort(h2) | ((uint32_t)__half_as_ushort(h3) << 16);
    hi[i] = make_uint2(ha, hb);
}

// w [K,N] row-major -> [N,K] (K-major), fp16
__global__ __launch_bounds__(256)
void transpose_h_kernel(const float* __restrict__ w, __half* __restrict__ hi,
                        int K, int N) {
    __shared__ float t[32][33];
    int n0 = blockIdx.x * 32, k0 = blockIdx.y * 32;
    int tx = threadIdx.x, ty = threadIdx.y;
#pragma unroll
    for (int i = 0; i < 4; i++)
        t[ty + i * 8][tx] = w[(size_t)(k0 + ty + i * 8) * N + n0 + tx];
    __syncthreads();
#pragma unroll
    for (int i = 0; i < 4; i++) {
        float v = t[tx][ty + i * 8];
        hi[(size_t)(n0 + ty + i * 8) * K + k0 + tx] = __float2half(v);
    }
}

// ---------------- mma.sync fp16 GEMM (BK=64, SW128 staging) ------------------
#define BKG 64
#define OPB (128 * 128)         // 16384 B per operand tile
#define STGB (2 * OPB)          // 32768 B per stage (A|B)
#define NSTG 3
#define GSMEM (NSTG * STGB)     // 98304 B

template<int EPI, typename OutT>
__global__ __launch_bounds__(256, 2)
void mgemm(const __half* __restrict__ Ah, const __half* __restrict__ Bh,
           const float* __restrict__ bias, const int* __restrict__ am,
           OutT* __restrict__ Cout, int N)
{
    extern __shared__ char smem_raw[];
    const uint32_t sbase = smem_u32(smem_raw);
    const int tid = threadIdx.x;
    const int wid = tid >> 5, lane = tid & 31;
    const int warp_row = wid & 1;        // 0..1 (64 rows each)
    const int warp_col = wid >> 1;       // 0..3 (32 cols each)
    const int bm = blockIdx.y * 128;
    const int bn = blockIdx.x * 128;

    float acc[4][4][4];
#pragma unroll
    for (int i = 0; i < 4; i++)
#pragma unroll
        for (int j = 0; j < 4; j++)
#pragma unroll
            for (int q = 0; q < 4; q++) acc[i][j][q] = 0.f;

    auto load_stage = [&](int s) {
        const int k0 = s * BKG;
        const uint32_t sb = sbase + (s % NSTG) * STGB;
#pragma unroll
        for (int i = 0; i < 4; i++) {
            int c = tid + i * 256;
            int row = c >> 3, ch = c & 7;
            uint32_t so = swz128((uint32_t)(row * 128 + ch * 16));
            size_t ga = (size_t)(bm + row) * KDIM + k0 + ch * 8;
            size_t gb = (size_t)(bn + row) * KDIM + k0 + ch * 8;
            cpasync16(sb + 0 * OPB + so, Ah + ga);
            cpasync16(sb + 1 * OPB + so, Bh + gb);
        }
        CP_COMMIT();
    };

    const int NS = KDIM / BKG;   // 16
    load_stage(0); load_stage(1);

    const int a_r = (lane & 7) + 8 * ((lane >> 3) & 1);
    const int a_k = 8 * (lane >> 4);
    const int b_r = (lane & 7) + 8 * (lane >> 4);
    const int b_k = 8 * ((lane >> 3) & 1);

    uint32_t aoff[4][4], boff[4][2];
#pragma unroll
    for (int kk = 0; kk < 4; kk++) {
#pragma unroll
        for (int mi = 0; mi < 4; mi++) {
            int r = warp_row * 64 + mi * 16 + a_r;
            aoff[kk][mi] = swz128((uint32_t)(r * 128 + (kk * 16 + a_k) * 2));
        }
#pragma unroll
        for (int p = 0; p < 2; p++) {
            int rn = warp_col * 32 + p * 16 + b_r;
            boff[kk][p] = OPB + swz128((uint32_t)(rn * 128 + (kk * 16 + b_k) * 2));
        }
    }

    for (int s = 0; s < NS; s++) {
        CP_WAIT1();
        __syncthreads();
        if (s + 2 < NS) load_stage(s + 2);

        const uint32_t sb = sbase + (s % NSTG) * STGB;

#pragma unroll
        for (int kk = 0; kk < 4; kk++) {
            uint32_t ah[4][4];
#pragma unroll
            for (int mi = 0; mi < 4; mi++)
                ldsm4(ah[mi], sb + aoff[kk][mi]);
            uint32_t bh0[4], bh1[4];
            ldsm4(bh0, sb + boff[kk][0]);
            ldsm4(bh1, sb + boff[kk][1]);
#pragma unroll
            for (int mi = 0; mi < 4; mi++)
#pragma unroll
                for (int j = 0; j < 2; j++)
                    mma16816(acc[mi][j], ah[mi], bh0[2 * j], bh0[2 * j + 1]);
#pragma unroll
            for (int mi = 0; mi < 4; mi++)
#pragma unroll
                for (int j = 0; j < 2; j++)
                    mma16816(acc[mi][2 + j], ah[mi], bh1[2 * j], bh1[2 * j + 1]);
        }
    }

    // epilogue (N-tile boundaries block-uniform)
    const bool isphi  = (EPI == 0) && (bn < 2048);
    const bool ismask = (EPI == 0) && (bn >= 1024);
    const int er = lane >> 2;
    const int ec = (lane & 3) * 2;
#pragma unroll
    for (int mi = 0; mi < 4; mi++) {
#pragma unroll
        for (int half = 0; half < 2; half++) {
            int row = bm + warp_row * 64 + mi * 16 + er + half * 8;
            float mv = 1.f;
            if (EPI == 0) mv = (am[row] > 0) ? 1.f : 0.f;
#pragma unroll
            for (int ni = 0; ni < 4; ni++) {
                int col = bn + warp_col * 32 + ni * 8 + ec;
                float v0 = acc[mi][ni][2 * half]     + bias[col];
                float v1 = acc[mi][ni][2 * half + 1] + bias[col + 1];
                if (EPI == 0) {
                    if (isphi) {
                        v0 = (v0 > 0.f) ? (v0 + 1.f) : fexp(v0);
                        v1 = (v1 > 0.f) ? (v1 + 1.f) : fexp(v1);
                    }
                    if (ismask) { v0 *= mv; v1 *= mv; }
                    __half2 hv = __halves2half2(__float2half(v0), __float2half(v1));
                    *(__half2*)((__half*)Cout + (size_t)row * N + col) = hv;
                } else {
                    *(float2*)((float*)Cout + (size_t)row * N + col) = make_float2(v0, v1);
                }
            }
        }
    }
}

// ---------------- K2: tensor-core kv = phi_k^T @ v per (bh, 256-t chunk) ----
__global__ __launch_bounds__(128)
void kv_mma_kernel(const __half* __restrict__ qkv, float* __restrict__ kvp,
                   float* __restrict__ ksp)
{
    __shared__ __half ksm[64 * 64];
    __shared__ __half vsm[64 * 64];
    __shared__ float  kcol[4][64];

    const int bh = blockIdx.x >> 3;
    const int chn = blockIdx.x & 7;
    const int b = bh >> 4, h = bh & 15;
    const int tid = threadIdx.x;
    const int wid = tid >> 5, lane = tid & 31;

    const uint32_t ksb = smem_u32(ksm);
    const uint32_t vsb = smem_u32(vsm);

    const __half* kb = qkv + (size_t)(b * TT + chn * 256) * N_QKV + 1024 + h * DD;
    const __half* vb = kb + 1024;

    float acc[8][4];
#pragma unroll
    for (int j = 0; j < 8; j++)
#pragma unroll
        for (int q = 0; q < 4; q++) acc[j][q] = 0.f;
    float ks0 = 0.f, ks1 = 0.f;

    const int at_r = (lane & 7) + 8 * (lane >> 4);
    const int at_c = 8 * ((lane >> 3) & 1);
    const int bt_r = (lane & 7) + 8 * ((lane >> 3) & 1);
    const int bt_c = 8 * (lane >> 4);

    for (int it = 0; it < 4; it++) {
        const int t0 = it * 64;
#pragma unroll
        for (int i = 0; i < 4; i++) {
            int c = tid + i * 128;
            int row = c >> 3, ch = c & 7;
            uint32_t so = swz128((uint32_t)(row * 128 + ch * 16));
            size_t go = (size_t)(t0 + row) * N_QKV + ch * 8;
            cpasync16(ksb + so, kb + go);
            cpasync16(vsb + so, vb + go);
        }
        CP_COMMIT(); CP_WAIT0();
        __syncthreads();

#pragma unroll
        for (int r = 0; r < 16; r++) {
            int row = wid * 16 + r;
            uint32_t w = *(uint32_t*)((char*)ksm + swz128((uint32_t)(row * 128 + lane * 4)));
            float2 f2 = __half22float2(*(__half2*)&w);
            ks0 += f2.x; ks1 += f2.y;
        }

#pragma unroll
        for (int kk = 0; kk < 4; kk++) {
            uint32_t A[4];
            {
                int trow = kk * 16 + at_r;
                int dcol = wid * 16 + at_c;
                ldsm4t(A, ksb + swz128((uint32_t)(trow * 128 + dcol * 2)));
            }
#pragma unroll
            for (int nt = 0; nt < 4; nt++) {
                int trow = kk * 16 + bt_r;
                int fcol = nt * 16 + bt_c;
                uint32_t Bv[4];
                ldsm4t(Bv, vsb + swz128((uint32_t)(trow * 128 + fcol * 2)));
                mma16816(acc[2 * nt],     A, Bv[0], Bv[1]);
                mma16816(acc[2 * nt + 1], A, Bv[2], Bv[3]);
            }
        }
        __syncthreads();
    }

    float* kvdst = kvp + ((size_t)chn * 128 + bh) * DD * DD;
    const int er = lane >> 2, ec = (lane & 3) * 2;
#pragma unroll
    for (int half = 0; half < 2; half++) {
        int drow = wid * 16 + er + half * 8;
#pragma unroll
        for (int nt8 = 0; nt8 < 8; nt8++) {
            *(float2*)(kvdst + drow * DD + nt8 * 8 + ec) =
                make_float2(acc[nt8][2 * half], acc[nt8][2 * half + 1]);
        }
    }
    kcol[wid][2 * lane] = ks0;
    kcol[wid][2 * lane + 1] = ks1;
    __syncthreads();
    if (tid < DD) {
        float s = kcol[0][tid] + kcol[1][tid] + kcol[2][tid] + kcol[3][tid];
        ksp[((size_t)chn * 128 + bh) * DD + tid] = s;
    }
}

// reduce partials -> kv as fp16 hi/lo + ksum fp32
__global__ __launch_bounds__(256)
void kv_reduce(const float* __restrict__ kvp, const float* __restrict__ ksp,
               __half* __restrict__ kvh, __half* __restrict__ kvl,
               float* __restrict__ ks)
{
    const int bh = blockIdx.x;
    const int tid = threadIdx.x;
    for (int i = tid; i < DD * DD; i += 256) {
        float s = 0.f;
#pragma unroll
        for (int c = 0; c < 8; c++) s += kvp[((size_t)c * 128 + bh) * DD * DD + i];
        __half h = __float2half(s);
        __half l = __float2half(s - __half2float(h));
        kvh[(size_t)bh * DD * DD + i] = h;
        kvl[(size_t)bh * DD * DD + i] = l;
    }
    if (tid < DD) {
        float s = 0.f;
#pragma unroll
        for (int c = 0; c < 8; c++) s += ksp[((size_t)c * 128 + bh) * DD + tid];
        ks[(size_t)bh * DD + tid] = s;
    }
}

// ---------------- K3: y = (phi_q @ kv) / max(phi_q . ksum, eps), tensor-core -
// 256 t-rows per block, 256 threads (8 warps x 32 rows). Dynamic smem:
// qs[256*128B]=32KB | kh 8KB | kl 8KB | kss 256B | dinv 1KB
#define YQS   0
#define YKH   32768
#define YKL   (YKH + 8192)
#define YKSS  (YKL + 8192)
#define YDINV (YKSS + 256)
#define YSMEM (YDINV + 1024)

__global__ __launch_bounds__(256)
void y_mma_kernel(const __half* __restrict__ qkv,
                  const __half* __restrict__ kvh, const __half* __restrict__ kvl,
                  const float* __restrict__ ksum, __half* __restrict__ yh)
{
    extern __shared__ char ysm[];
    const uint32_t base = smem_u32(ysm);
    const uint32_t qsb = base + YQS;
    const uint32_t khb = base + YKH;
    const uint32_t klb = base + YKL;
    float* kss  = (float*)(ysm + YKSS);
    float* dinv = (float*)(ysm + YDINV);

    const int bh = blockIdx.y;
    const int b = bh >> 4, h = bh & 15;
    const int t0 = blockIdx.x * 256;
    const int tid = threadIdx.x;
    const int wid = tid >> 5, lane = tid & 31;

    {
        const int ch = tid & 7, rb = tid >> 3;     // rb 0..31
#pragma unroll
        for (int i = 0; i < 8; i++) {
            int row = rb + 32 * i;                 // 0..255
            const __half* src = qkv + (size_t)(b * TT + t0 + row) * N_QKV + h * DD + ch * 8;
            cpasync16(qsb + swz128((uint32_t)(row * 128 + ch * 16)), src);
        }
#pragma unroll
        for (int i = 0; i < 2; i++) {
            int row = rb + 32 * i;                 // 0..63
            size_t go = (size_t)bh * DD * DD + row * DD + ch * 8;
            uint32_t so = swz128((uint32_t)(row * 128 + ch * 16));
            cpasync16(khb + so, kvh + go);
            cpasync16(klb + so, kvl + go);
        }
        CP_COMMIT();
    }
    if (tid < DD) kss[tid] = ksum[bh * DD + tid];
    CP_WAIT0();
    __syncthreads();

    // denominator for own row (256 rows, one per thread)
    {
        float den = 0.f;
#pragma unroll
        for (int c = 0; c < 8; c++) {
            uint4 v = *(uint4*)(ysm + YQS + swz128((uint32_t)(tid * 128 + c * 16)));
            uint32_t w[4] = {v.x, v.y, v.z, v.w};
#pragma unroll
            for (int j = 0; j < 4; j++) {
                float2 f2 = __half22float2(*(__half2*)&w[j]);
                den = fmaf(f2.x, kss[c * 8 + 2 * j],     den);
                den = fmaf(f2.y, kss[c * 8 + 2 * j + 1], den);
            }
        }
        dinv[tid] = 1.f / fmaxf(den, 1e-8f);
    }
    __syncthreads();

    float acc[2][8][4];
#pragma unroll
    for (int i = 0; i < 2; i++)
#pragma unroll
        for (int j = 0; j < 8; j++)
#pragma unroll
            for (int q = 0; q < 4; q++) acc[i][j][q] = 0.f;

    const int a_r = (lane & 7) + 8 * ((lane >> 3) & 1);
    const int a_c = 16 * (lane >> 4);
    const int t_r = (lane & 7) + 8 * ((lane >> 3) & 1);
    const int t_c = 16 * (lane >> 4);

#pragma unroll
    for (int kk = 0; kk < 4; kk++) {
        uint32_t A[2][4];
#pragma unroll
        for (int mi = 0; mi < 2; mi++) {
            int row = wid * 32 + mi * 16 + a_r;
            ldsm4(A[mi], qsb + swz128((uint32_t)(row * 128 + kk * 32 + a_c)));
        }
#pragma unroll
        for (int nt = 0; nt < 4; nt++) {
            int drow = kk * 16 + t_r;
            uint32_t so = swz128((uint32_t)(drow * 128 + nt * 32 + t_c));
            uint32_t Bh[4], Bl[4];
            ldsm4t(Bh, khb + so);
            ldsm4t(Bl, klb + so);
#pragma unroll
            for (int mi = 0; mi < 2; mi++) {
                mma16816(acc[mi][2 * nt],     A[mi], Bh[0], Bh[1]);
                mma16816(acc[mi][2 * nt + 1], A[mi], Bh[2], Bh[3]);
                mma16816(acc[mi][2 * nt],     A[mi], Bl[0], Bl[1]);
                mma16816(acc[mi][2 * nt + 1], A[mi], Bl[2], Bl[3]);
            }
        }
    }

    const int er = lane >> 2;
    const int ec = (lane & 3) * 2;
#pragma unroll
    for (int mi = 0; mi < 2; mi++) {
#pragma unroll
        for (int half = 0; half < 2; half++) {
            int lrow = wid * 32 + mi * 16 + er + half * 8;
            float di = dinv[lrow];
            size_t gro = (size_t)(b * TT + t0 + lrow) * CC + h * DD;
#pragma unroll
            for (int nt8 = 0; nt8 < 8; nt8++) {
                float v0 = acc[mi][nt8][2 * half]     * di;
                float v1 = acc[mi][nt8][2 * half + 1] * di;
                __half2 hv = __halves2half2(__float2half(v0), __float2half(v1));
                *(__half2*)(yh + gro + nt8 * 8 + ec) = hv;
            }
        }
    }
}

// ---------------------------------------------------------------------------
extern "C" void kernel_launch(void* const* d_in, const int* in_sizes, int n_in,
                              void* d_out, int out_size)
{
    const float* x      = (const float*)d_in[0];
    const int*   am     = (const int*)  d_in[1];
    const float* w_attn = (const float*)d_in[2];
    const float* b_attn = (const float*)d_in[3];
    const float* w_proj = (const float*)d_in[4];
    const float* b_proj = (const float*)d_in[5];
    float* out = (float*)d_out;

    float *kvp, *ksp, *ksb;
    __half *qkv, *xh, *wah, *wph, *yh, *kvh, *kvl;
    cudaGetSymbolAddress((void**)&qkv, g_qkv);
    cudaGetSymbolAddress((void**)&xh,  g_xh);
    cudaGetSymbolAddress((void**)&wah, g_wah);
    cudaGetSymbolAddress((void**)&wph, g_wph);
    cudaGetSymbolAddress((void**)&yh,  g_yh);
    cudaGetSymbolAddress((void**)&kvp, g_kvp);
    cudaGetSymbolAddress((void**)&ksp, g_ksp);
    cudaGetSymbolAddress((void**)&kvh, g_kvh);
    cudaGetSymbolAddress((void**)&kvl, g_kvl);
    cudaGetSymbolAddress((void**)&ksb, g_ks);

    cudaFuncSetAttribute(mgemm<0, __half>, cudaFuncAttributeMaxDynamicSharedMemorySize, GSMEM);
    cudaFuncSetAttribute(mgemm<1, float>,  cudaFuncAttributeMaxDynamicSharedMemorySize, GSMEM);
    cudaFuncSetAttribute(y_mma_kernel,     cudaFuncAttributeMaxDynamicSharedMemorySize, YSMEM);

    // fp16 conversions
    conv_x_kernel<<<(MTOT * KDIM / 4) / 256, 256>>>((const float4*)x, (uint2*)xh);
    transpose_h_kernel<<<dim3(N_QKV / 32, KDIM / 32), dim3(32, 8)>>>(w_attn, wah, KDIM, N_QKV);
    transpose_h_kernel<<<dim3(N_PROJ / 32, KDIM / 32), dim3(32, 8)>>>(w_proj, wph, KDIM, N_PROJ);

    // K1: qkv = x @ w_attn + b_attn (mma.sync fp16), fused phi/mask, fp16 out
    mgemm<0, __half><<<dim3(N_QKV / 128, MTOT / 128), 256, GSMEM>>>(xh, wah, b_attn, am, qkv, N_QKV);
    // K2: per-head kv state + ksum (tensor-core, 8 T-chunks, then reduce)
    kv_mma_kernel<<<BB * HH * 8, 128>>>(qkv, kvp, ksp);
    kv_reduce<<<BB * HH, 256>>>(kvp, ksp, kvh, kvl, ksb);
    // K3: normalized linear attention output -> y (tensor-core, 256 rows/blk)
    y_mma_kernel<<<dim3(TT / 256, BB * HH), 256, YSMEM>>>(qkv, kvh, kvl, ksb, yh);
    // K4: out = y @ w_proj + b_proj (mma.sync fp16), fp32 out
    mgemm<1, float><<<dim3(N_PROJ / 128, MTOT / 128), 256, GSMEM>>>(yh, wph, b_proj, nullptr, out, N_PROJ);
}

// round 17
// speedup vs baseline: 1.0084x; 1.0084x over previous
#include <cuda_runtime.h>
#include <cuda_fp16.h>
#include <math.h>
#include <stdint.h>

// Problem shape
#define BB 8
#define TT 2048
#define CC 1024
#define HH 16
#define DD 64
#define MTOT (BB*TT)      // 16384
#define KDIM 1024
#define N_QKV 3072
#define N_PROJ 1024

// ---------------- scratch (__device__ globals; no allocation allowed) -------
__device__ __half g_qkv [(size_t)MTOT * N_QKV];   // fp16: phi_q | phi_k*m | v*m
__device__ __half g_xh  [(size_t)MTOT * KDIM];
__device__ __half g_wah [(size_t)N_QKV * KDIM];   // transposed [N,K], fp16
__device__ __half g_wph [(size_t)N_PROJ * KDIM];
__device__ __half g_yh  [(size_t)MTOT * CC];
__device__ float  g_kvp[8 * BB*HH * DD*DD];
__device__ float  g_ksp[8 * BB*HH * DD];
__device__ __half g_kvh[BB*HH * DD*DD];           // kv state fp16 hi
__device__ __half g_kvl[BB*HH * DD*DD];           // kv state fp16 lo
__device__ float  g_ks [BB*HH * DD];

// ---------------- helpers ----------------------------------------------------
__device__ __forceinline__ uint32_t smem_u32(const void* p) {
    uint32_t a;
    asm("{ .reg .u64 t; cvta.to.shared.u64 t, %1; cvt.u32.u64 %0, t; }"
        : "=r"(a) : "l"(p));
    return a;
}
__device__ __forceinline__ void cpasync16(uint32_t dst, const void* src) {
    asm volatile("cp.async.cg.shared.global [%0], [%1], 16;" :: "r"(dst), "l"(src));
}
#define CP_COMMIT() asm volatile("cp.async.commit_group;" ::: "memory")
#define CP_WAIT1()  asm volatile("cp.async.wait_group 1;" ::: "memory")
#define CP_WAIT0()  asm volatile("cp.async.wait_group 0;" ::: "memory")

__device__ __forceinline__ void ldsm4(uint32_t (&r)[4], uint32_t addr) {
    asm volatile("ldmatrix.sync.aligned.m8n8.x4.shared.b16 {%0,%1,%2,%3}, [%4];"
                 : "=r"(r[0]), "=r"(r[1]), "=r"(r[2]), "=r"(r[3]) : "r"(addr));
}
__device__ __forceinline__ void ldsm4t(uint32_t (&r)[4], uint32_t addr) {
    asm volatile("ldmatrix.sync.aligned.m8n8.x4.trans.shared.b16 {%0,%1,%2,%3}, [%4];"
                 : "=r"(r[0]), "=r"(r[1]), "=r"(r[2]), "=r"(r[3]) : "r"(addr));
}
__device__ __forceinline__ void mma16816(float (&c)[4], const uint32_t (&a)[4],
                                         uint32_t b0, uint32_t b1) {
    asm volatile(
        "mma.sync.aligned.m16n8k16.row.col.f32.f16.f16.f32 "
        "{%0,%1,%2,%3}, {%4,%5,%6,%7}, {%8,%9}, {%0,%1,%2,%3};"
        : "+f"(c[0]), "+f"(c[1]), "+f"(c[2]), "+f"(c[3])
        : "r"(a[0]), "r"(a[1]), "r"(a[2]), "r"(a[3]), "r"(b0), "r"(b1));
}

// FFMA-only exp(x) (no MUFU), rel err ~2.4e-6.
__device__ __forceinline__ float fexp(float x) {
    x = fmaxf(x, -80.f);
    float t = x * 1.4426950408889634f;
    float r = t + 12582912.0f;
    int   n = __float_as_int(r) - 0x4B400000;
    float f = t - (r - 12582912.0f);
    float g = f * 0.6931471805599453f;
    float p = fmaf(g, 0.008333333f, 0.041666667f);
    p = fmaf(g, p, 0.166666667f);
    p = fmaf(g, p, 0.5f);
    p = fmaf(g, p, 1.0f);
    p = fmaf(g, p, 1.0f);
    return __int_as_float(__float_as_int(p) + (n << 23));
}

// SW128 swizzle for 128B rows (Swizzle<3,4,3>)
__device__ __forceinline__ uint32_t swz128(uint32_t o) {
    return o ^ ((o >> 3) & 0x70);
}

// ---------------- conversion kernels ----------------------------------------
__global__ __launch_bounds__(256)
void conv_x_kernel(const float4* __restrict__ in, uint2* __restrict__ hi) {
    size_t i = (size_t)blockIdx.x * blockDim.x + threadIdx.x;
    float4 v = in[i];
    __half h0 = __float2half(v.x), h1 = __float2half(v.y);
    __half h2 = __float2half(v.z), h3 = __float2half(v.w);
    uint32_t ha = (uint32_t)__half_as_ushort(h0) | ((uint32_t)__half_as_ushort(h1) << 16);
    uint32_t hb = (uint32_t)__half_as_ushort(h2) | ((uint32_t)__half_as_ushort(h3) << 16);
    hi[i] = make_uint2(ha, hb);
}

// w [K,N] row-major -> [N,K] (K-major), fp16
__global__ __launch_bounds__(256)
void transpose_h_kernel(const float* __restrict__ w, __half* __restrict__ hi,
                        int K, int N) {
    __shared__ float t[32][33];
    int n0 = blockIdx.x * 32, k0 = blockIdx.y * 32;
    int tx = threadIdx.x, ty = threadIdx.y;
#pragma unroll
    for (int i = 0; i < 4; i++)
        t[ty + i * 8][tx] = w[(size_t)(k0 + ty + i * 8) * N + n0 + tx];
    __syncthreads();
#pragma unroll
    for (int i = 0; i < 4; i++) {
        float v = t[tx][ty + i * 8];
        hi[(size_t)(n0 + ty + i * 8) * K + k0 + tx] = __float2half(v);
    }
}

// ---------------- mma.sync fp16 GEMM (BK=64, SW128 staging) ------------------
#define BKG 64
#define OPB (128 * 128)         // 16384 B per operand tile
#define STGB (2 * OPB)          // 32768 B per stage (A|B)
#define NSTG 3
#define GSMEM (NSTG * STGB)     // 98304 B

template<int EPI, typename OutT>
__global__ __launch_bounds__(256, 2)
void mgemm(const __half* __restrict__ Ah, const __half* __restrict__ Bh,
           const float* __restrict__ bias, const int* __restrict__ am,
           OutT* __restrict__ Cout, int N, int bn0)
{
    extern __shared__ char smem_raw[];
    const uint32_t sbase = smem_u32(smem_raw);
    const int tid = threadIdx.x;
    const int wid = tid >> 5, lane = tid & 31;
    const int warp_row = wid & 1;        // 0..1 (64 rows each)
    const int warp_col = wid >> 1;       // 0..3 (32 cols each)
    const int bm = blockIdx.y * 128;
    const int bn = bn0 + blockIdx.x * 128;

    float acc[4][4][4];
#pragma unroll
    for (int i = 0; i < 4; i++)
#pragma unroll
        for (int j = 0; j < 4; j++)
#pragma unroll
            for (int q = 0; q < 4; q++) acc[i][j][q] = 0.f;

    auto load_stage = [&](int s) {
        const int k0 = s * BKG;
        const uint32_t sb = sbase + (s % NSTG) * STGB;
#pragma unroll
        for (int i = 0; i < 4; i++) {
            int c = tid + i * 256;
            int row = c >> 3, ch = c & 7;
            uint32_t so = swz128((uint32_t)(row * 128 + ch * 16));
            size_t ga = (size_t)(bm + row) * KDIM + k0 + ch * 8;
            size_t gb = (size_t)(bn + row) * KDIM + k0 + ch * 8;
            cpasync16(sb + 0 * OPB + so, Ah + ga);
            cpasync16(sb + 1 * OPB + so, Bh + gb);
        }
        CP_COMMIT();
    };

    const int NS = KDIM / BKG;   // 16
    load_stage(0); load_stage(1);

    const int a_r = (lane & 7) + 8 * ((lane >> 3) & 1);
    const int a_k = 8 * (lane >> 4);
    const int b_r = (lane & 7) + 8 * (lane >> 4);
    const int b_k = 8 * ((lane >> 3) & 1);

    uint32_t aoff[4][4], boff[4][2];
#pragma unroll
    for (int kk = 0; kk < 4; kk++) {
#pragma unroll
        for (int mi = 0; mi < 4; mi++) {
            int r = warp_row * 64 + mi * 16 + a_r;
            aoff[kk][mi] = swz128((uint32_t)(r * 128 + (kk * 16 + a_k) * 2));
        }
#pragma unroll
        for (int p = 0; p < 2; p++) {
            int rn = warp_col * 32 + p * 16 + b_r;
            boff[kk][p] = OPB + swz128((uint32_t)(rn * 128 + (kk * 16 + b_k) * 2));
        }
    }

    for (int s = 0; s < NS; s++) {
        CP_WAIT1();
        __syncthreads();
        if (s + 2 < NS) load_stage(s + 2);

        const uint32_t sb = sbase + (s % NSTG) * STGB;

#pragma unroll
        for (int kk = 0; kk < 4; kk++) {
            uint32_t ah[4][4];
#pragma unroll
            for (int mi = 0; mi < 4; mi++)
                ldsm4(ah[mi], sb + aoff[kk][mi]);
            uint32_t bh0[4], bh1[4];
            ldsm4(bh0, sb + boff[kk][0]);
            ldsm4(bh1, sb + boff[kk][1]);
#pragma unroll
            for (int mi = 0; mi < 4; mi++)
#pragma unroll
                for (int j = 0; j < 2; j++)
                    mma16816(acc[mi][j], ah[mi], bh0[2 * j], bh0[2 * j + 1]);
#pragma unroll
            for (int mi = 0; mi < 4; mi++)
#pragma unroll
                for (int j = 0; j < 2; j++)
                    mma16816(acc[mi][2 + j], ah[mi], bh1[2 * j], bh1[2 * j + 1]);
        }
    }

    // epilogue (N-tile boundaries block-uniform)
    const bool isphi  = (EPI == 0) && (bn < 2048);
    const bool ismask = (EPI == 0) && (bn >= 1024);
    const int er = lane >> 2;
    const int ec = (lane & 3) * 2;
#pragma unroll
    for (int mi = 0; mi < 4; mi++) {
#pragma unroll
        for (int half = 0; half < 2; half++) {
            int row = bm + warp_row * 64 + mi * 16 + er + half * 8;
            float mv = 1.f;
            if (EPI == 0) mv = (am[row] > 0) ? 1.f : 0.f;
#pragma unroll
            for (int ni = 0; ni < 4; ni++) {
                int col = bn + warp_col * 32 + ni * 8 + ec;
                float v0 = acc[mi][ni][2 * half]     + bias[col];
                float v1 = acc[mi][ni][2 * half + 1] + bias[col + 1];
                if (EPI == 0) {
                    if (isphi) {
                        v0 = (v0 > 0.f) ? (v0 + 1.f) : fexp(v0);
                        v1 = (v1 > 0.f) ? (v1 + 1.f) : fexp(v1);
                    }
                    if (ismask) { v0 *= mv; v1 *= mv; }
                    __half2 hv = __halves2half2(__float2half(v0), __float2half(v1));
                    *(__half2*)((__half*)Cout + (size_t)row * N + col) = hv;
                } else {
                    *(float2*)((float*)Cout + (size_t)row * N + col) = make_float2(v0, v1);
                }
            }
        }
    }
}

// ---------------- K2: tensor-core kv = phi_k^T @ v per (bh, 256-t chunk) ----
__global__ __launch_bounds__(128)
void kv_mma_kernel(const __half* __restrict__ qkv, float* __restrict__ kvp,
                   float* __restrict__ ksp)
{
    __shared__ __half ksm[64 * 64];
    __shared__ __half vsm[64 * 64];
    __shared__ float  kcol[4][64];

    const int bh = blockIdx.x >> 3;
    const int chn = blockIdx.x & 7;
    const int b = bh >> 4, h = bh & 15;
    const int tid = threadIdx.x;
    const int wid = tid >> 5, lane = tid & 31;

    const uint32_t ksb = smem_u32(ksm);
    const uint32_t vsb = smem_u32(vsm);

    const __half* kb = qkv + (size_t)(b * TT + chn * 256) * N_QKV + 1024 + h * DD;
    const __half* vb = kb + 1024;

    float acc[8][4];
#pragma unroll
    for (int j = 0; j < 8; j++)
#pragma unroll
        for (int q = 0; q < 4; q++) acc[j][q] = 0.f;
    float ks0 = 0.f, ks1 = 0.f;

    const int at_r = (lane & 7) + 8 * (lane >> 4);
    const int at_c = 8 * ((lane >> 3) & 1);
    const int bt_r = (lane & 7) + 8 * ((lane >> 3) & 1);
    const int bt_c = 8 * (lane >> 4);

    for (int it = 0; it < 4; it++) {
        const int t0 = it * 64;
#pragma unroll
        for (int i = 0; i < 4; i++) {
            int c = tid + i * 128;
            int row = c >> 3, ch = c & 7;
            uint32_t so = swz128((uint32_t)(row * 128 + ch * 16));
            size_t go = (size_t)(t0 + row) * N_QKV + ch * 8;
            cpasync16(ksb + so, kb + go);
            cpasync16(vsb + so, vb + go);
        }
        CP_COMMIT(); CP_WAIT0();
        __syncthreads();

#pragma unroll
        for (int r = 0; r < 16; r++) {
            int row = wid * 16 + r;
            uint32_t w = *(uint32_t*)((char*)ksm + swz128((uint32_t)(row * 128 + lane * 4)));
            float2 f2 = __half22float2(*(__half2*)&w);
            ks0 += f2.x; ks1 += f2.y;
        }

#pragma unroll
        for (int kk = 0; kk < 4; kk++) {
            uint32_t A[4];
            {
                int trow = kk * 16 + at_r;
                int dcol = wid * 16 + at_c;
                ldsm4t(A, ksb + swz128((uint32_t)(trow * 128 + dcol * 2)));
            }
#pragma unroll
            for (int nt = 0; nt < 4; nt++) {
                int trow = kk * 16 + bt_r;
                int fcol = nt * 16 + bt_c;
                uint32_t Bv[4];
                ldsm4t(Bv, vsb + swz128((uint32_t)(trow * 128 + fcol * 2)));
                mma16816(acc[2 * nt],     A, Bv[0], Bv[1]);
                mma16816(acc[2 * nt + 1], A, Bv[2], Bv[3]);
            }
        }
        __syncthreads();
    }

    float* kvdst = kvp + ((size_t)chn * 128 + bh) * DD * DD;
    const int er = lane >> 2, ec = (lane & 3) * 2;
#pragma unroll
    for (int half = 0; half < 2; half++) {
        int drow = wid * 16 + er + half * 8;
#pragma unroll
        for (int nt8 = 0; nt8 < 8; nt8++) {
            *(float2*)(kvdst + drow * DD + nt8 * 8 + ec) =
                make_float2(acc[nt8][2 * half], acc[nt8][2 * half + 1]);
        }
    }
    kcol[wid][2 * lane] = ks0;
    kcol[wid][2 * lane + 1] = ks1;
    __syncthreads();
    if (tid < DD) {
        float s = kcol[0][tid] + kcol[1][tid] + kcol[2][tid] + kcol[3][tid];
        ksp[((size_t)chn * 128 + bh) * DD + tid] = s;
    }
}

// reduce partials -> kv as fp16 hi/lo + ksum fp32
__global__ __launch_bounds__(256)
void kv_reduce(const float* __restrict__ kvp, const float* __restrict__ ksp,
               __half* __restrict__ kvh, __half* __restrict__ kvl,
               float* __restrict__ ks)
{
    const int bh = blockIdx.x;
    const int tid = threadIdx.x;
    for (int i = tid; i < DD * DD; i += 256) {
        float s = 0.f;
#pragma unroll
        for (int c = 0; c < 8; c++) s += kvp[((size_t)c * 128 + bh) * DD * DD + i];
        __half h = __float2half(s);
        __half l = __float2half(s - __half2float(h));
        kvh[(size_t)bh * DD * DD + i] = h;
        kvl[(size_t)bh * DD * DD + i] = l;
    }
    if (tid < DD) {
        float s = 0.f;
#pragma unroll
        for (int c = 0; c < 8; c++) s += ksp[((size_t)c * 128 + bh) * DD + tid];
        ks[(size_t)bh * DD + tid] = s;
    }
}

// ---------------- K3: y = (phi_q @ kv) / max(phi_q . ksum, eps), tensor-core -
__global__ __launch_bounds__(128)
void y_mma_kernel(const __half* __restrict__ qkv,
                  const __half* __restrict__ kvh, const __half* __restrict__ kvl,
                  const float* __restrict__ ksum, __half* __restrict__ yh)
{
    __shared__ __half qs[128 * 64];
    __shared__ __half kh[64 * 64];
    __shared__ __half kl[64 * 64];
    __shared__ float  kss[DD];
    __shared__ float  dinv[128];

    const int bh = blockIdx.y;
    const int b = bh >> 4, h = bh & 15;
    const int t0 = blockIdx.x * 128;
    const int tid = threadIdx.x;
    const int wid = tid >> 5, lane = tid & 31;

    const uint32_t qsb = smem_u32(qs);
    const uint32_t khb = smem_u32(kh);
    const uint32_t klb = smem_u32(kl);

    {
        const int ch = tid & 7, rb = tid >> 3;
#pragma unroll
        for (int i = 0; i < 8; i++) {
            int row = rb + 16 * i;
            const __half* src = qkv + (size_t)(b * TT + t0 + row) * N_QKV + h * DD + ch * 8;
            cpasync16(qsb + swz128((uint32_t)(row * 128 + ch * 16)), src);
        }
#pragma unroll
        for (int i = 0; i < 4; i++) {
            int row = rb + 16 * i;
            size_t go = (size_t)bh * DD * DD + row * DD + ch * 8;
            uint32_t so = swz128((uint32_t)(row * 128 + ch * 16));
            cpasync16(khb + so, kvh + go);
            cpasync16(klb + so, kvl + go);
        }
        CP_COMMIT();
    }
    if (tid < DD) kss[tid] = ksum[bh * DD + tid];
    CP_WAIT0();
    __syncthreads();

    {
        float den = 0.f;
#pragma unroll
        for (int c = 0; c < 8; c++) {
            uint4 v = *(uint4*)((char*)qs + swz128((uint32_t)(tid * 128 + c * 16)));
            uint32_t w[4] = {v.x, v.y, v.z, v.w};
#pragma unroll
            for (int j = 0; j < 4; j++) {
                float2 f2 = __half22float2(*(__half2*)&w[j]);
                den = fmaf(f2.x, kss[c * 8 + 2 * j],     den);
                den = fmaf(f2.y, kss[c * 8 + 2 * j + 1], den);
            }
        }
        dinv[tid] = 1.f / fmaxf(den, 1e-8f);
    }
    __syncthreads();

    float acc[2][8][4];
#pragma unroll
    for (int i = 0; i < 2; i++)
#pragma unroll
        for (int j = 0; j < 8; j++)
#pragma unroll
            for (int q = 0; q < 4; q++) acc[i][j][q] = 0.f;

    const int a_r = (lane & 7) + 8 * ((lane >> 3) & 1);
    const int a_c = 16 * (lane >> 4);
    const int t_r = (lane & 7) + 8 * ((lane >> 3) & 1);
    const int t_c = 16 * (lane >> 4);

#pragma unroll
    for (int kk = 0; kk < 4; kk++) {
        uint32_t A[2][4];
#pragma unroll
        for (int mi = 0; mi < 2; mi++) {
            int row = wid * 32 + mi * 16 + a_r;
            ldsm4(A[mi], qsb + swz128((uint32_t)(row * 128 + kk * 32 + a_c)));
        }
#pragma unroll
        for (int nt = 0; nt < 4; nt++) {
            int drow = kk * 16 + t_r;
            uint32_t so = swz128((uint32_t)(drow * 128 + nt * 32 + t_c));
            uint32_t Bh[4], Bl[4];
            ldsm4t(Bh, khb + so);
            ldsm4t(Bl, klb + so);
#pragma unroll
            for (int mi = 0; mi < 2; mi++) {
                mma16816(acc[mi][2 * nt],     A[mi], Bh[0], Bh[1]);
                mma16816(acc[mi][2 * nt + 1], A[mi], Bh[2], Bh[3]);
                mma16816(acc[mi][2 * nt],     A[mi], Bl[0], Bl[1]);
                mma16816(acc[mi][2 * nt + 1], A[mi], Bl[2], Bl[3]);
            }
        }
    }

    const int er = lane >> 2;
    const int ec = (lane & 3) * 2;
#pragma unroll
    for (int mi = 0; mi < 2; mi++) {
#pragma unroll
        for (int half = 0; half < 2; half++) {
            int lrow = wid * 32 + mi * 16 + er + half * 8;
            float di = dinv[lrow];
            size_t gro = (size_t)(b * TT + t0 + lrow) * CC + h * DD;
#pragma unroll
            for (int nt8 = 0; nt8 < 8; nt8++) {
                float v0 = acc[mi][nt8][2 * half]     * di;
                float v1 = acc[mi][nt8][2 * half + 1] * di;
                __half2 hv = __halves2half2(__float2half(v0), __float2half(v1));
                *(__half2*)(yh + gro + nt8 * 8 + ec) = hv;
            }
        }
    }
}

// ---------------------------------------------------------------------------
extern "C" void kernel_launch(void* const* d_in, const int* in_sizes, int n_in,
                              void* d_out, int out_size)
{
    const float* x      = (const float*)d_in[0];
    const int*   am     = (const int*)  d_in[1];
    const float* w_attn = (const float*)d_in[2];
    const float* b_attn = (const float*)d_in[3];
    const float* w_proj = (const float*)d_in[4];
    const float* b_proj = (const float*)d_in[5];
    float* out = (float*)d_out;

    float *kvp, *ksp, *ksb;
    __half *qkv, *xh, *wah, *wph, *yh, *kvh, *kvl;
    cudaGetSymbolAddress((void**)&qkv, g_qkv);
    cudaGetSymbolAddress((void**)&xh,  g_xh);
    cudaGetSymbolAddress((void**)&wah, g_wah);
    cudaGetSymbolAddress((void**)&wph, g_wph);
    cudaGetSymbolAddress((void**)&yh,  g_yh);
    cudaGetSymbolAddress((void**)&kvp, g_kvp);
    cudaGetSymbolAddress((void**)&ksp, g_ksp);
    cudaGetSymbolAddress((void**)&kvh, g_kvh);
    cudaGetSymbolAddress((void**)&kvl, g_kvl);
    cudaGetSymbolAddress((void**)&ksb, g_ks);

    cudaFuncSetAttribute(mgemm<0, __half>, cudaFuncAttributeMaxDynamicSharedMemorySize, GSMEM);
    cudaFuncSetAttribute(mgemm<1, float>,  cudaFuncAttributeMaxDynamicSharedMemorySize, GSMEM);

    // fork/join streams + events (lazily created once; host-side handles only)
    static cudaStream_t sW = nullptr, sKV = nullptr;
    static cudaEvent_t eRoot = nullptr, eWA = nullptr, eWP = nullptr,
                       eQKV = nullptr, eKV = nullptr;
    if (!sW) {
        cudaStreamCreateWithFlags(&sW,  cudaStreamNonBlocking);
        cudaStreamCreateWithFlags(&sKV, cudaStreamNonBlocking);
        cudaEventCreateWithFlags(&eRoot, cudaEventDisableTiming);
        cudaEventCreateWithFlags(&eWA,   cudaEventDisableTiming);
        cudaEventCreateWithFlags(&eWP,   cudaEventDisableTiming);
        cudaEventCreateWithFlags(&eQKV,  cudaEventDisableTiming);
        cudaEventCreateWithFlags(&eKV,   cudaEventDisableTiming);
    }

    // fork: weight transposes on sW, overlapping conv_x on main
    cudaEventRecord(eRoot, 0);
    cudaStreamWaitEvent(sW, eRoot, 0);
    transpose_h_kernel<<<dim3(N_QKV / 32, KDIM / 32), dim3(32, 8), 0, sW>>>(w_attn, wah, KDIM, N_QKV);
    cudaEventRecord(eWA, sW);
    transpose_h_kernel<<<dim3(N_PROJ / 32, KDIM / 32), dim3(32, 8), 0, sW>>>(w_proj, wph, KDIM, N_PROJ);
    cudaEventRecord(eWP, sW);

    // main: x fp32 -> fp16
    conv_x_kernel<<<(MTOT * KDIM / 4) / 256, 256>>>((const float4*)x, (uint2*)xh);
    cudaStreamWaitEvent(0, eWA, 0);

    // main: K1a — k/v columns of qkv first (cols 1024..3071)
    mgemm<0, __half><<<dim3(16, MTOT / 128), 256, GSMEM>>>(xh, wah, b_attn, am, qkv, N_QKV, 1024);
    cudaEventRecord(eQKV, 0);

    // fork: kv chain on sKV, overlapping K1b on main
    cudaStreamWaitEvent(sKV, eQKV, 0);
    kv_mma_kernel<<<BB * HH * 8, 128, 0, sKV>>>(qkv, kvp, ksp);
    kv_reduce<<<BB * HH, 256, 0, sKV>>>(kvp, ksp, kvh, kvl, ksb);
    cudaEventRecord(eKV, sKV);

    // main: K1b — q columns (cols 0..1023)
    mgemm<0, __half><<<dim3(8, MTOT / 128), 256, GSMEM>>>(xh, wah, b_attn, am, qkv, N_QKV, 0);

    // join: y needs q columns + kv state
    cudaStreamWaitEvent(0, eKV, 0);
    y_mma_kernel<<<dim3(TT / 128, BB * HH), 128>>>(qkv, kvh, kvl, ksb, yh);

    // join: proj weight, then final GEMM
    cudaStreamWaitEvent(0, eWP, 0);
    mgemm<1, float><<<dim3(N_PROJ / 128, MTOT / 128), 256, GSMEM>>>(yh, wph, b_proj, nullptr, out, N_PROJ, 0);
}